// round 5
// baseline (speedup 1.0000x reference)
#include <cuda_runtime.h>
#include <cstdint>

// Problem constants
#define B_   128
#define T_   512
#define D_   256
#define H_   512
#define G_   2048          // 4*H
#define K0_  768           // D + H (layer0 concat K)
#define K1_  1024          // H + H (layer1 concat K)
#define NCTA 128
#define BH   (B_ * H_)

// ---------------- persistent device scratch ----------------------------------
__device__ float g_W0T[(size_t)K0_ * G_];   // [k][n'] k-major, gate-interleaved, proj folded
__device__ float g_W1T[(size_t)K1_ * G_];
__device__ float g_b0[G_];
__device__ float g_b1[G_];
// h state double buffers: h0b0, h0b1, h1b0, h1b1
__device__ float g_state[4 * BH];
__device__ unsigned g_count;
__device__ unsigned g_release;

// ---------------- helpers ----------------------------------------------------
__device__ __forceinline__ unsigned long long packdup(float w) {
    unsigned long long r;
    unsigned u = __float_as_uint(w);
    asm("mov.b64 %0, {%1, %1};" : "=l"(r) : "r"(u));
    return r;
}
__device__ __forceinline__ void ffma2(unsigned long long& d,
                                      unsigned long long a,
                                      unsigned long long b) {
    asm("fma.rn.f32x2 %0, %1, %2, %0;" : "+l"(d) : "l"(a), "l"(b));
}
__device__ __forceinline__ float2 unpack2(unsigned long long v) {
    unsigned lo, hi;
    asm("mov.b64 {%0, %1}, %2;" : "=r"(lo), "=r"(hi) : "l"(v));
    return make_float2(__uint_as_float(lo), __uint_as_float(hi));
}
__device__ __forceinline__ float sigm(float v) { return 1.f / (1.f + __expf(-v)); }

// swizzled offset into [64][128] staged input tile: row k, col b (b low 2 bits free)
__device__ __forceinline__ int swz(int k, int b) {
    return (k << 7) + (b ^ (((k >> 2) & 7) << 2));
}

__device__ __forceinline__ void gridBarrier(unsigned target) {
    __syncthreads();
    if (threadIdx.x == 0) {
        __threadfence();
        unsigned t = atomicAdd(&g_count, 1u);
        if (t == (unsigned)(NCTA - 1)) {
            g_count = 0;
            __threadfence();
            atomicAdd(&g_release, 1u);
        } else {
            while ((int)(*(volatile unsigned*)&g_release - target) < 0) {}
        }
        __threadfence();
    }
    __syncthreads();
}

// ---------------- weight preparation (unchanged from R1, validated) ----------
__global__ void prep_w0(const float* __restrict__ wx0, const float* __restrict__ projw,
                        const float* __restrict__ projb, const float* __restrict__ bx0,
                        const float* __restrict__ bh0) {
    int np = blockIdx.x;                 // n'
    int jcol = np >> 2, q = np & 3;
    int n = q * H_ + jcol;
    int d = threadIdx.x;                 // 0..255
    const float* wrow = wx0 + (size_t)n * D_;
    float acc = 0.f;
    for (int j = 0; j < D_; ++j) acc += wrow[j] * projw[(size_t)j * D_ + d];
    g_W0T[(size_t)d * G_ + np] = acc;
    if (d == 0) {
        float bb = bx0[n] + bh0[n];
        for (int j = 0; j < D_; ++j) bb += wrow[j] * projb[j];
        g_b0[np] = bb;
    }
}

__global__ void prep_copy(const float* __restrict__ wh0, const float* __restrict__ wx1,
                          const float* __restrict__ wh1, const float* __restrict__ bx1,
                          const float* __restrict__ bh1) {
    const int total = H_ * G_ + K1_ * G_ + G_;
    for (int i = blockIdx.x * blockDim.x + threadIdx.x; i < total;
         i += gridDim.x * blockDim.x) {
        if (i < H_ * G_) {
            int k = i / G_, np = i % G_;
            int n = (np & 3) * H_ + (np >> 2);
            g_W0T[(size_t)(D_ + k) * G_ + np] = wh0[(size_t)n * H_ + k];
        } else if (i < H_ * G_ + K1_ * G_) {
            int r = i - H_ * G_;
            int k = r / G_, np = r % G_;
            int n = (np & 3) * H_ + (np >> 2);
            float v = (k < H_) ? wx1[(size_t)n * H_ + k] : wh1[(size_t)n * H_ + (k - H_)];
            g_W1T[(size_t)k * G_ + np] = v;
        } else {
            int np = i - H_ * G_ - K1_ * G_;
            int n = (np & 3) * H_ + (np >> 2);
            g_b1[np] = bx1[n] + bh1[n];
        }
    }
}

// ---------------- slice primitives --------------------------------------------
// LDG a 64-k x 128-b input slice into registers (k-contiguous per thread: coalesced)
template <int LEN1>
__device__ __forceinline__ void ldg_slice(float4 (&r)[8], int s,
    const float* __restrict__ src1, int st1, const float* __restrict__ src2,
    int kc, int sb) {
    int k0 = s * 64;
    const float* src; int st;
    if (k0 < LEN1) { src = src1 + k0; st = st1; }
    else           { src = src2 + (k0 - LEN1); st = H_; }
    const float* p = src + (kc << 2) + (size_t)sb * st;
#pragma unroll
    for (int rr = 0; rr < 8; ++rr)
        r[rr] = *(const float4*)(p + (size_t)rr * 16 * st);
}

// transpose-store regs into swizzled smem tile (2-way max bank conflict)
__device__ __forceinline__ void sts_slice(float* __restrict__ buf,
                                          const float4 (&r)[8], int kc, int sb) {
    int kl = kc << 2;
#pragma unroll
    for (int rr = 0; rr < 8; ++rr) {
        int b = sb + (rr << 4);
        buf[swz(kl + 0, b)] = r[rr].x;
        buf[swz(kl + 1, b)] = r[rr].y;
        buf[swz(kl + 2, b)] = r[rr].z;
        buf[swz(kl + 3, b)] = r[rr].w;
    }
}

// 64-k compute: 16 outputs/thread (4 batch x 4 gates) as 8 f32x2 accumulators
__device__ __forceinline__ void comp_slice(unsigned long long (&acc)[2][4],
    const float* __restrict__ buf, const float* __restrict__ wk, int trow4) {
#pragma unroll 16
    for (int k = 0; k < 64; ++k) {
        ulonglong2 hp = *(const ulonglong2*)(buf + swz(k, trow4));
        float4 wv = *(const float4*)(wk + (k << 5));
        unsigned long long w0 = packdup(wv.x), w1 = packdup(wv.y);
        unsigned long long w2 = packdup(wv.z), w3 = packdup(wv.w);
        ffma2(acc[0][0], hp.x, w0); ffma2(acc[1][0], hp.y, w0);
        ffma2(acc[0][1], hp.x, w1); ffma2(acc[1][1], hp.y, w1);
        ffma2(acc[0][2], hp.x, w2); ffma2(acc[1][2], hp.y, w2);
        ffma2(acc[0][3], hp.x, w3); ffma2(acc[1][3], hp.y, w3);
    }
}

// ---------------- one LSTM layer step (GEMM + cell epilogue) ------------------
// tile: [128 batch x 32 gate-cols], weights resident in sh_w, c in registers.
template <int KSZ, int LEN1>
__device__ void lstm_phase(const float* __restrict__ sh_w,
    float* __restrict__ bufA, float* __restrict__ bufB,
    const float* __restrict__ src1, int st1, const float* __restrict__ src2,
    float* __restrict__ hOut, float* __restrict__ cc,
    float4 bias, int jcol0) {
    const int tid = threadIdx.x;
    const int tcol = tid & 7, trow4 = (tid >> 3) << 2;
    const int kc = tid & 15, sb = tid >> 4;

    unsigned long long acc[2][4];
    acc[0][0] = packdup(bias.x); acc[0][1] = packdup(bias.y);
    acc[0][2] = packdup(bias.z); acc[0][3] = packdup(bias.w);
#pragma unroll
    for (int q = 0; q < 4; ++q) acc[1][q] = acc[0][q];

    constexpr int NS = KSZ / 64;
    float4 r[8];
    ldg_slice<LEN1>(r, 0, src1, st1, src2, kc, sb);
    sts_slice(bufA, r, kc, sb);
    __syncthreads();

#pragma unroll 1
    for (int s = 0; s < NS; ++s) {
        if (s + 1 < NS) ldg_slice<LEN1>(r, s + 1, src1, st1, src2, kc, sb);
        comp_slice(acc, (s & 1) ? bufB : bufA,
                   sh_w + s * 64 * 32 + (tcol << 2), trow4);
        __syncthreads();
        if (s + 1 < NS) {
            sts_slice(((s + 1) & 1) ? bufB : bufA, r, kc, sb);
            __syncthreads();
        }
    }

    // LSTM cell epilogue: 4 cells/thread, c in registers
#pragma unroll
    for (int p = 0; p < 2; ++p) {
        float2 gi = unpack2(acc[p][0]);
        float2 gf = unpack2(acc[p][1]);
        float2 gg = unpack2(acc[p][2]);
        float2 go = unpack2(acc[p][3]);
#pragma unroll
        for (int e = 0; e < 2; ++e) {
            int bi = (p << 1) + e;
            float iv = e ? gi.y : gi.x, fv = e ? gf.y : gf.x;
            float gv = e ? gg.y : gg.x, ov = e ? go.y : go.x;
            float cn = sigm(fv) * cc[bi] + sigm(iv) * tanhf(gv);
            cc[bi] = cn;
            hOut[(size_t)(trow4 + bi) * H_ + jcol0 + tcol] = sigm(ov) * tanhf(cn);
        }
    }
}

// ---------------- persistent main kernel --------------------------------------
// CTAs [0,64): layer0 step t=phase ; CTAs [64,128): layer1 step t=phase-1.
// Weights smem-resident for the whole kernel; one grid barrier per phase.
__global__ void __launch_bounds__(256, 1) lstm_main(const float* __restrict__ x) {
    extern __shared__ float smem[];
    float* sh_w = smem;                     // up to 1024 x 32 floats (128 KB)
    float* bufA = smem + 1024 * 32;         // 64 x 128 (32 KB)
    float* bufB = bufA + 64 * 128;          // 64 x 128 (32 KB)

    const int cta = blockIdx.x, tid = threadIdx.x;
    unsigned relBase = *(volatile unsigned*)&g_release;
    unsigned gen = 0;

    const bool isL1 = (cta >= 64);
    const int lc = isL1 ? cta - 64 : cta;
    const int n0 = lc * 32;
    const int jcol0 = lc * 8;

    // load resident weight tile (once per kernel)
    const float* gW = isL1 ? g_W1T : g_W0T;
    const int Kk = isL1 ? K1_ : K0_;
    for (int i = tid; i < Kk * 8; i += 256) {
        int k = i >> 3, c2 = (i & 7) << 2;
        *(float4*)(sh_w + k * 32 + c2) = *(const float4*)(gW + (size_t)k * G_ + n0 + c2);
    }
    const float* gb = isL1 ? g_b1 : g_b0;
    float4 bias = *(const float4*)(gb + n0 + ((tid & 7) << 2));

    // zero h buffers each launch (deterministic)
    for (int i = cta * 256 + tid; i < 4 * BH; i += NCTA * 256) g_state[i] = 0.f;

    float cc[4] = {0.f, 0.f, 0.f, 0.f};   // register-resident cell state

    gridBarrier(relBase + ++gen);

    float* h0b0 = g_state;
    float* h0b1 = g_state + BH;
    float* h1b0 = g_state + 2 * BH;
    float* h1b1 = g_state + 3 * BH;

    for (int phase = 0; phase <= T_; ++phase) {
        if (!isL1) {
            if (phase < T_) {
                int t = phase;
                const float* hprev = (t & 1) ? h0b0 : h0b1;   // h0(t-1)
                float* hout        = (t & 1) ? h0b1 : h0b0;   // h0(t)
                lstm_phase<K0_, D_>(sh_w, bufA, bufB,
                                    x + (size_t)t * D_, T_ * D_,
                                    hprev, hout, cc, bias, jcol0);
            }
        } else {
            if (phase >= 1) {
                int t = phase - 1;
                const float* h0cur  = (t & 1) ? h0b1 : h0b0;  // h0(t)
                const float* h1prev = (t & 1) ? h1b0 : h1b1;  // h1(t-1)
                float* hout         = (t & 1) ? h1b1 : h1b0;  // h1(t)
                lstm_phase<K1_, H_>(sh_w, bufA, bufB,
                                    h0cur, H_, h1prev, hout, cc, bias, jcol0);
            }
        }
        gridBarrier(relBase + ++gen);
    }
}

// ---------------- FC head ------------------------------------------------------
__global__ void fc_head(const float* __restrict__ fc1w, const float* __restrict__ fc1b,
                        const float* __restrict__ fc2w, const float* __restrict__ fc2b,
                        float* __restrict__ out) {
    __shared__ float hsh[H_];
    __shared__ float hid[32];
    int b = blockIdx.x, tid = threadIdx.x;  // 256 threads
    const float* h = g_state + 3 * BH + (size_t)b * H_;  // final h1 (t=511 odd -> buf1)
    hsh[tid] = h[tid];
    hsh[tid + 256] = h[tid + 256];
    __syncthreads();
    int w = tid >> 5, lane = tid & 31;
    for (int j = w; j < 32; j += 8) {
        const float* wr = fc1w + (size_t)j * H_;
        float s = 0.f;
        for (int k = lane; k < H_; k += 32) s += hsh[k] * wr[k];
#pragma unroll
        for (int off = 16; off; off >>= 1) s += __shfl_xor_sync(0xffffffffu, s, off);
        if (lane == 0) hid[j] = fmaxf(s + fc1b[j], 0.f) * fc2w[j];
    }
    __syncthreads();
    if (tid < 32) {
        float v = hid[tid];
#pragma unroll
        for (int off = 16; off; off >>= 1) v += __shfl_xor_sync(0xffffffffu, v, off);
        if (tid == 0) out[b] = v + fc2b[0];
    }
}

// ---------------- launch --------------------------------------------------------
extern "C" void kernel_launch(void* const* d_in, const int* in_sizes, int n_in,
                              void* d_out, int out_size) {
    const float* x     = (const float*)d_in[0];
    const float* projw = (const float*)d_in[1];
    const float* projb = (const float*)d_in[2];
    const float* wx0   = (const float*)d_in[3];
    const float* bx0   = (const float*)d_in[4];
    const float* wh0   = (const float*)d_in[5];
    const float* bh0   = (const float*)d_in[6];
    const float* wx1   = (const float*)d_in[7];
    const float* bx1   = (const float*)d_in[8];
    const float* wh1   = (const float*)d_in[9];
    const float* bh1   = (const float*)d_in[10];
    const float* fc1w  = (const float*)d_in[11];
    const float* fc1b  = (const float*)d_in[12];
    const float* fc2w  = (const float*)d_in[13];
    const float* fc2b  = (const float*)d_in[14];
    float* out = (float*)d_out;

    const int SMEM_BYTES = (1024 * 32 + 2 * 64 * 128) * 4;  // 196608
    cudaFuncSetAttribute(lstm_main, cudaFuncAttributeMaxDynamicSharedMemorySize,
                         SMEM_BYTES);

    prep_w0<<<G_, D_>>>(wx0, projw, projb, bx0, bh0);
    prep_copy<<<1024, 256>>>(wh0, wx1, wh1, bx1, bh1);
    lstm_main<<<NCTA, 256, SMEM_BYTES>>>(x);
    fc_head<<<B_, 256>>>(fc1w, fc1b, fc2w, fc2b, out);
}

// round 6
// speedup vs baseline: 1.0031x; 1.0031x over previous
#include <cuda_runtime.h>
#include <cstdint>

// Problem constants
#define B_   128
#define T_   512
#define D_   256
#define H_   512
#define G_   2048          // 4*H
#define K0_  768           // D + H (layer0 concat K)
#define K1_  1024          // H + H (layer1 concat K)
#define NCTA 128
#define BH   (B_ * H_)

// ---------------- persistent device scratch ----------------------------------
__device__ float g_W0T[(size_t)K0_ * G_];   // [k][n'] k-major, gate-interleaved, proj folded
__device__ float g_W1T[(size_t)K1_ * G_];
__device__ float g_b0[G_];
__device__ float g_b1[G_];
// h state double buffers: h0b0, h0b1, h1b0, h1b1
__device__ float g_state[4 * BH];
__device__ unsigned g_count;
__device__ unsigned g_release;

// ---------------- helpers ----------------------------------------------------
__device__ __forceinline__ unsigned long long packdup(float w) {
    unsigned long long r;
    unsigned u = __float_as_uint(w);
    asm("mov.b64 %0, {%1, %1};" : "=l"(r) : "r"(u));
    return r;
}
__device__ __forceinline__ void ffma2(unsigned long long& d,
                                      unsigned long long a,
                                      unsigned long long b) {
    asm("fma.rn.f32x2 %0, %1, %2, %0;" : "+l"(d) : "l"(a), "l"(b));
}
__device__ __forceinline__ float2 unpack2(unsigned long long v) {
    unsigned lo, hi;
    asm("mov.b64 {%0, %1}, %2;" : "=r"(lo), "=r"(hi) : "l"(v));
    return make_float2(__uint_as_float(lo), __uint_as_float(hi));
}
__device__ __forceinline__ float sigm(float v) { return 1.f / (1.f + __expf(-v)); }

// swizzled offset into [64][128] staged input tile: row k, col b (b low 2 bits free)
__device__ __forceinline__ int swz(int k, int b) {
    return (k << 7) + (b ^ (((k >> 2) & 7) << 2));
}

__device__ __forceinline__ void gridBarrier(unsigned target) {
    __syncthreads();
    if (threadIdx.x == 0) {
        __threadfence();
        unsigned t = atomicAdd(&g_count, 1u);
        if (t == (unsigned)(NCTA - 1)) {
            g_count = 0;
            __threadfence();
            atomicAdd(&g_release, 1u);
        } else {
            while ((int)(*(volatile unsigned*)&g_release - target) < 0) {}
        }
        __threadfence();
    }
    __syncthreads();
}

// ---------------- weight preparation (unchanged from R1, validated) ----------
__global__ void prep_w0(const float* __restrict__ wx0, const float* __restrict__ projw,
                        const float* __restrict__ projb, const float* __restrict__ bx0,
                        const float* __restrict__ bh0) {
    int np = blockIdx.x;                 // n'
    int jcol = np >> 2, q = np & 3;
    int n = q * H_ + jcol;
    int d = threadIdx.x;                 // 0..255
    const float* wrow = wx0 + (size_t)n * D_;
    float acc = 0.f;
    for (int j = 0; j < D_; ++j) acc += wrow[j] * projw[(size_t)j * D_ + d];
    g_W0T[(size_t)d * G_ + np] = acc;
    if (d == 0) {
        float bb = bx0[n] + bh0[n];
        for (int j = 0; j < D_; ++j) bb += wrow[j] * projb[j];
        g_b0[np] = bb;
    }
}

__global__ void prep_copy(const float* __restrict__ wh0, const float* __restrict__ wx1,
                          const float* __restrict__ wh1, const float* __restrict__ bx1,
                          const float* __restrict__ bh1) {
    const int total = H_ * G_ + K1_ * G_ + G_;
    for (int i = blockIdx.x * blockDim.x + threadIdx.x; i < total;
         i += gridDim.x * blockDim.x) {
        if (i < H_ * G_) {
            int k = i / G_, np = i % G_;
            int n = (np & 3) * H_ + (np >> 2);
            g_W0T[(size_t)(D_ + k) * G_ + np] = wh0[(size_t)n * H_ + k];
        } else if (i < H_ * G_ + K1_ * G_) {
            int r = i - H_ * G_;
            int k = r / G_, np = r % G_;
            int n = (np & 3) * H_ + (np >> 2);
            float v = (k < H_) ? wx1[(size_t)n * H_ + k] : wh1[(size_t)n * H_ + (k - H_)];
            g_W1T[(size_t)k * G_ + np] = v;
        } else {
            int np = i - H_ * G_ - K1_ * G_;
            int n = (np & 3) * H_ + (np >> 2);
            g_b1[np] = bx1[n] + bh1[n];
        }
    }
}

// ---------------- slice primitives --------------------------------------------
// LDG a 64-k x 128-b input slice into registers (k-contiguous per thread: coalesced)
template <int LEN1>
__device__ __forceinline__ void ldg_slice(float4 (&r)[8], int s,
    const float* __restrict__ src1, int st1, const float* __restrict__ src2,
    int kc, int sb) {
    int k0 = s * 64;
    const float* src; int st;
    if (k0 < LEN1) { src = src1 + k0; st = st1; }
    else           { src = src2 + (k0 - LEN1); st = H_; }
    const float* p = src + (kc << 2) + (size_t)sb * st;
#pragma unroll
    for (int rr = 0; rr < 8; ++rr)
        r[rr] = *(const float4*)(p + (size_t)rr * 16 * st);
}

// transpose-store regs into swizzled smem tile (2-way max bank conflict)
__device__ __forceinline__ void sts_slice(float* __restrict__ buf,
                                          const float4 (&r)[8], int kc, int sb) {
    int kl = kc << 2;
#pragma unroll
    for (int rr = 0; rr < 8; ++rr) {
        int b = sb + (rr << 4);
        buf[swz(kl + 0, b)] = r[rr].x;
        buf[swz(kl + 1, b)] = r[rr].y;
        buf[swz(kl + 2, b)] = r[rr].z;
        buf[swz(kl + 3, b)] = r[rr].w;
    }
}

// 64-k compute: 16 outputs/thread (4 batch x 4 gates) as 8 f32x2 accumulators
__device__ __forceinline__ void comp_slice(unsigned long long (&acc)[2][4],
    const float* __restrict__ buf, const float* __restrict__ wk, int trow4) {
#pragma unroll 16
    for (int k = 0; k < 64; ++k) {
        ulonglong2 hp = *(const ulonglong2*)(buf + swz(k, trow4));
        float4 wv = *(const float4*)(wk + (k << 5));
        unsigned long long w0 = packdup(wv.x), w1 = packdup(wv.y);
        unsigned long long w2 = packdup(wv.z), w3 = packdup(wv.w);
        ffma2(acc[0][0], hp.x, w0); ffma2(acc[1][0], hp.y, w0);
        ffma2(acc[0][1], hp.x, w1); ffma2(acc[1][1], hp.y, w1);
        ffma2(acc[0][2], hp.x, w2); ffma2(acc[1][2], hp.y, w2);
        ffma2(acc[0][3], hp.x, w3); ffma2(acc[1][3], hp.y, w3);
    }
}

// ---------------- one LSTM layer step (GEMM + cell epilogue) ------------------
// tile: [128 batch x 32 gate-cols], weights resident in sh_w, c in registers.
template <int KSZ, int LEN1>
__device__ void lstm_phase(const float* __restrict__ sh_w,
    float* __restrict__ bufA, float* __restrict__ bufB,
    const float* __restrict__ src1, int st1, const float* __restrict__ src2,
    float* __restrict__ hOut, float* __restrict__ cc,
    float4 bias, int jcol0) {
    const int tid = threadIdx.x;
    const int tcol = tid & 7, trow4 = (tid >> 3) << 2;
    const int kc = tid & 15, sb = tid >> 4;

    unsigned long long acc[2][4];
    acc[0][0] = packdup(bias.x); acc[0][1] = packdup(bias.y);
    acc[0][2] = packdup(bias.z); acc[0][3] = packdup(bias.w);
#pragma unroll
    for (int q = 0; q < 4; ++q) acc[1][q] = acc[0][q];

    constexpr int NS = KSZ / 64;
    float4 r[8];
    ldg_slice<LEN1>(r, 0, src1, st1, src2, kc, sb);
    sts_slice(bufA, r, kc, sb);
    __syncthreads();

#pragma unroll 1
    for (int s = 0; s < NS; ++s) {
        if (s + 1 < NS) ldg_slice<LEN1>(r, s + 1, src1, st1, src2, kc, sb);
        comp_slice(acc, (s & 1) ? bufB : bufA,
                   sh_w + s * 64 * 32 + (tcol << 2), trow4);
        __syncthreads();
        if (s + 1 < NS) {
            sts_slice(((s + 1) & 1) ? bufB : bufA, r, kc, sb);
            __syncthreads();
        }
    }

    // LSTM cell epilogue: 4 cells/thread, c in registers
#pragma unroll
    for (int p = 0; p < 2; ++p) {
        float2 gi = unpack2(acc[p][0]);
        float2 gf = unpack2(acc[p][1]);
        float2 gg = unpack2(acc[p][2]);
        float2 go = unpack2(acc[p][3]);
#pragma unroll
        for (int e = 0; e < 2; ++e) {
            int bi = (p << 1) + e;
            float iv = e ? gi.y : gi.x, fv = e ? gf.y : gf.x;
            float gv = e ? gg.y : gg.x, ov = e ? go.y : go.x;
            float cn = sigm(fv) * cc[bi] + sigm(iv) * tanhf(gv);
            cc[bi] = cn;
            hOut[(size_t)(trow4 + bi) * H_ + jcol0 + tcol] = sigm(ov) * tanhf(cn);
        }
    }
}

// ---------------- persistent main kernel --------------------------------------
// CTAs [0,64): layer0 step t=phase ; CTAs [64,128): layer1 step t=phase-1.
// Weights smem-resident for the whole kernel; one grid barrier per phase.
__global__ void __launch_bounds__(256, 1) lstm_main(const float* __restrict__ x) {
    extern __shared__ float smem[];
    float* sh_w = smem;                     // up to 1024 x 32 floats (128 KB)
    float* bufA = smem + 1024 * 32;         // 64 x 128 (32 KB)
    float* bufB = bufA + 64 * 128;          // 64 x 128 (32 KB)

    const int cta = blockIdx.x, tid = threadIdx.x;
    unsigned relBase = *(volatile unsigned*)&g_release;
    unsigned gen = 0;

    const bool isL1 = (cta >= 64);
    const int lc = isL1 ? cta - 64 : cta;
    const int n0 = lc * 32;
    const int jcol0 = lc * 8;

    // load resident weight tile (once per kernel)
    const float* gW = isL1 ? g_W1T : g_W0T;
    const int Kk = isL1 ? K1_ : K0_;
    for (int i = tid; i < Kk * 8; i += 256) {
        int k = i >> 3, c2 = (i & 7) << 2;
        *(float4*)(sh_w + k * 32 + c2) = *(const float4*)(gW + (size_t)k * G_ + n0 + c2);
    }
    const float* gb = isL1 ? g_b1 : g_b0;
    float4 bias = *(const float4*)(gb + n0 + ((tid & 7) << 2));

    // zero h buffers each launch (deterministic)
    for (int i = cta * 256 + tid; i < 4 * BH; i += NCTA * 256) g_state[i] = 0.f;

    float cc[4] = {0.f, 0.f, 0.f, 0.f};   // register-resident cell state

    gridBarrier(relBase + ++gen);

    float* h0b0 = g_state;
    float* h0b1 = g_state + BH;
    float* h1b0 = g_state + 2 * BH;
    float* h1b1 = g_state + 3 * BH;

    for (int phase = 0; phase <= T_; ++phase) {
        if (!isL1) {
            if (phase < T_) {
                int t = phase;
                const float* hprev = (t & 1) ? h0b0 : h0b1;   // h0(t-1)
                float* hout        = (t & 1) ? h0b1 : h0b0;   // h0(t)
                lstm_phase<K0_, D_>(sh_w, bufA, bufB,
                                    x + (size_t)t * D_, T_ * D_,
                                    hprev, hout, cc, bias, jcol0);
            }
        } else {
            if (phase >= 1) {
                int t = phase - 1;
                const float* h0cur  = (t & 1) ? h0b1 : h0b0;  // h0(t)
                const float* h1prev = (t & 1) ? h1b0 : h1b1;  // h1(t-1)
                float* hout         = (t & 1) ? h1b1 : h1b0;  // h1(t)
                lstm_phase<K1_, H_>(sh_w, bufA, bufB,
                                    h0cur, H_, h1prev, hout, cc, bias, jcol0);
            }
        }
        gridBarrier(relBase + ++gen);
    }
}

// ---------------- FC head ------------------------------------------------------
__global__ void fc_head(const float* __restrict__ fc1w, const float* __restrict__ fc1b,
                        const float* __restrict__ fc2w, const float* __restrict__ fc2b,
                        float* __restrict__ out) {
    __shared__ float hsh[H_];
    __shared__ float hid[32];
    int b = blockIdx.x, tid = threadIdx.x;  // 256 threads
    const float* h = g_state + 3 * BH + (size_t)b * H_;  // final h1 (t=511 odd -> buf1)
    hsh[tid] = h[tid];
    hsh[tid + 256] = h[tid + 256];
    __syncthreads();
    int w = tid >> 5, lane = tid & 31;
    for (int j = w; j < 32; j += 8) {
        const float* wr = fc1w + (size_t)j * H_;
        float s = 0.f;
        for (int k = lane; k < H_; k += 32) s += hsh[k] * wr[k];
#pragma unroll
        for (int off = 16; off; off >>= 1) s += __shfl_xor_sync(0xffffffffu, s, off);
        if (lane == 0) hid[j] = fmaxf(s + fc1b[j], 0.f) * fc2w[j];
    }
    __syncthreads();
    if (tid < 32) {
        float v = hid[tid];
#pragma unroll
        for (int off = 16; off; off >>= 1) v += __shfl_xor_sync(0xffffffffu, v, off);
        if (tid == 0) out[b] = v + fc2b[0];
    }
}

// ---------------- launch --------------------------------------------------------
extern "C" void kernel_launch(void* const* d_in, const int* in_sizes, int n_in,
                              void* d_out, int out_size) {
    const float* x     = (const float*)d_in[0];
    const float* projw = (const float*)d_in[1];
    const float* projb = (const float*)d_in[2];
    const float* wx0   = (const float*)d_in[3];
    const float* bx0   = (const float*)d_in[4];
    const float* wh0   = (const float*)d_in[5];
    const float* bh0   = (const float*)d_in[6];
    const float* wx1   = (const float*)d_in[7];
    const float* bx1   = (const float*)d_in[8];
    const float* wh1   = (const float*)d_in[9];
    const float* bh1   = (const float*)d_in[10];
    const float* fc1w  = (const float*)d_in[11];
    const float* fc1b  = (const float*)d_in[12];
    const float* fc2w  = (const float*)d_in[13];
    const float* fc2b  = (const float*)d_in[14];
    float* out = (float*)d_out;

    const int SMEM_BYTES = (1024 * 32 + 2 * 64 * 128) * 4;  // 196608
    cudaFuncSetAttribute(lstm_main, cudaFuncAttributeMaxDynamicSharedMemorySize,
                         SMEM_BYTES);

    prep_w0<<<G_, D_>>>(wx0, projw, projb, bx0, bh0);
    prep_copy<<<1024, 256>>>(wh0, wx1, wh1, bx1, bh1);
    lstm_main<<<NCTA, 256, SMEM_BYTES>>>(x);
    fc_head<<<B_, 256>>>(fc1w, fc1b, fc2w, fc2b, out);
}

// round 8
// speedup vs baseline: 1.6125x; 1.6074x over previous
#include <cuda_runtime.h>
#include <cuda_bf16.h>
#include <cstdint>

#define B_   128
#define T_   512
#define D_   256
#define H_   512
#define G_   2048
#define K0_  768
#define K1_  1024
#define NKT0 (K0_ / 16)      // 48 ktiles
#define NKT1 (K1_ / 16)      // 64 ktiles
#define NCTA 128
#define BH   (B_ * H_)

// ---------------- persistent device scratch -----------------------------------
// Weight fragments, B-frag lane order: [ntg(256)][kt][s=hi/lo][lane(32)][4 bf16]
__device__ uint4 g_Wf0[(size_t)256 * NKT0 * 2 * 16];   // 6 MB
__device__ uint4 g_Wf1[(size_t)256 * NKT1 * 2 * 16];   // 8 MB
__device__ float g_b0[G_];
__device__ float g_b1[G_];
__device__ uint32_t g_xp[(size_t)T_ * B_ * D_];        // packed hi|lo<<16, [t][b][d]
__device__ uint32_t g_hp[2][2][BH];                    // [layer][buf][b*H + col]
__device__ unsigned g_count;
__device__ unsigned g_release;

// ---------------- helpers -------------------------------------------------------
__device__ __forceinline__ float sigm(float v) { return 1.f / (1.f + __expf(-v)); }

__device__ __forceinline__ uint32_t pack_split(float v) {
    __nv_bfloat16 h = __float2bfloat16(v);
    __nv_bfloat16 l = __float2bfloat16(v - __bfloat162float(h));
    return (uint32_t)__bfloat16_as_ushort(h) |
           ((uint32_t)__bfloat16_as_ushort(l) << 16);
}

__device__ __forceinline__ uint32_t prmt(uint32_t a, uint32_t b, uint32_t c) {
    uint32_t r;
    asm("prmt.b32 %0, %1, %2, %3;" : "=r"(r) : "r"(a), "r"(b), "r"(c));
    return r;
}

__device__ __forceinline__ void mma16816(float* d, const uint32_t* a, uint2 b) {
    asm volatile(
        "mma.sync.aligned.m16n8k16.row.col.f32.bf16.bf16.f32 "
        "{%0,%1,%2,%3}, {%4,%5,%6,%7}, {%8,%9}, {%0,%1,%2,%3};"
        : "+f"(d[0]), "+f"(d[1]), "+f"(d[2]), "+f"(d[3])
        : "r"(a[0]), "r"(a[1]), "r"(a[2]), "r"(a[3]), "r"(b.x), "r"(b.y));
}

__device__ __forceinline__ void gridBarrier(unsigned target) {
    __syncthreads();
    if (threadIdx.x == 0) {
        __threadfence();
        unsigned t = atomicAdd(&g_count, 1u);
        if (t == (unsigned)(NCTA - 1)) {
            g_count = 0;
            __threadfence();
            atomicAdd(&g_release, 1u);
        } else {
            while ((int)(*(volatile unsigned*)&g_release - target) < 0) {}
        }
        __threadfence();
    }
    __syncthreads();
}

// bf16-split store of W[np][k] into fragment layout (hi plane + lo plane)
__device__ __forceinline__ void wf_store(__nv_bfloat16* base, int NKT,
                                         int np, int k, float v) {
    __nv_bfloat16 h = __float2bfloat16(v);
    __nv_bfloat16 l = __float2bfloat16(v - __bfloat162float(h));
    int ntg = np >> 3;
    int ln = ((np & 7) << 2) | ((k >> 1) & 3);   // B-frag: n = lane/4, k-pair = lane%4
    int kt = k >> 4, b = (k >> 3) & 1, e = k & 1;
    size_t o = ((((size_t)ntg * NKT + kt) * 2) * 32 + ln) * 4 + b * 2 + e;
    base[o] = h;
    base[o + 128] = l;   // s=1 plane is +32*4 elements
}

// ---------------- prep kernels ---------------------------------------------------
__global__ void prep_x(const float* __restrict__ x) {
    const size_t total = (size_t)T_ * B_ * D_;
    for (size_t i = (size_t)blockIdx.x * blockDim.x + threadIdx.x; i < total;
         i += (size_t)gridDim.x * blockDim.x) {
        int t = (int)(i / (B_ * D_));
        int r = (int)(i % (B_ * D_));
        int b = r / D_, d = r % D_;
        g_xp[i] = pack_split(x[(size_t)b * T_ * D_ + (size_t)t * D_ + d]);
    }
}

// W0[np][k<256] = folded proj; b0
__global__ void prep_w0(const float* __restrict__ wx0, const float* __restrict__ projw,
                        const float* __restrict__ projb, const float* __restrict__ bx0,
                        const float* __restrict__ bh0) {
    int np = blockIdx.x;
    int jcol = np >> 2, q = np & 3;
    int n = q * H_ + jcol;
    int d = threadIdx.x;
    const float* wrow = wx0 + (size_t)n * D_;
    float acc = 0.f;
    for (int j = 0; j < D_; ++j) acc += wrow[j] * projw[(size_t)j * D_ + d];
    wf_store((__nv_bfloat16*)g_Wf0, NKT0, np, d, acc);
    if (d == 0) {
        float bb = bx0[n] + bh0[n];
        for (int j = 0; j < D_; ++j) bb += wrow[j] * projb[j];
        g_b0[np] = bb;
    }
}

// W0[np][k>=256] = wh0 ; W1 = [wx1|wh1] ; b1
__global__ void prep_rest(const float* __restrict__ wh0, const float* __restrict__ wx1,
                          const float* __restrict__ wh1, const float* __restrict__ bx1,
                          const float* __restrict__ bh1) {
    const int total = G_ * H_ + G_ * K1_ + G_;
    for (int i = blockIdx.x * blockDim.x + threadIdx.x; i < total;
         i += gridDim.x * blockDim.x) {
        if (i < G_ * H_) {
            int np = i / H_, k = i % H_;
            int n = (np & 3) * H_ + (np >> 2);
            wf_store((__nv_bfloat16*)g_Wf0, NKT0, np, D_ + k,
                     wh0[(size_t)n * H_ + k]);
        } else if (i < G_ * H_ + G_ * K1_) {
            int r = i - G_ * H_;
            int np = r / K1_, k = r % K1_;
            int n = (np & 3) * H_ + (np >> 2);
            float v = (k < H_) ? wx1[(size_t)n * H_ + k]
                               : wh1[(size_t)n * H_ + (k - H_)];
            wf_store((__nv_bfloat16*)g_Wf1, NKT1, np, k, v);
        } else {
            int np = i - G_ * H_ - G_ * K1_;
            int n = (np & 3) * H_ + (np >> 2);
            g_b1[np] = bx1[n] + bh1[n];
        }
    }
}

// ---------------- A fragment loads (packed u32, direct from global) -------------
__device__ __forceinline__ void ldA(uint2* a, int kt,
    const uint32_t* __restrict__ s1, int st1,
    const uint32_t* __restrict__ s2, int len1, int r0, int kq) {
    int kb = kt << 4;
    const uint32_t* s;
    int st;
    if (kb < len1) { s = s1 + kb + kq; st = st1; }
    else           { s = s2 + (kb - len1) + kq; st = H_; }
    const uint32_t* p0 = s + (size_t)r0 * st;
#pragma unroll
    for (int mt = 0; mt < 2; ++mt)
#pragma unroll
        for (int rp = 0; rp < 2; ++rp) {
            const uint32_t* p = p0 + (size_t)(mt * 16 + rp * 8) * st;
            a[mt * 4 + rp]     = *(const uint2*)p;        // a0/a1: k pair
            a[mt * 4 + rp + 2] = *(const uint2*)(p + 8);  // a2/a3: k pair + 8
        }
}

// ---------------- one LSTM phase: bf16-split mma + cell epilogue -----------------
template <int NKT>
__device__ void lstm_phase(const uint32_t* __restrict__ sW,
    const uint32_t* __restrict__ src1, int st1,
    const uint32_t* __restrict__ src2, int len1,
    uint32_t* __restrict__ hOut, float* cst,
    const float* __restrict__ sbias, uint32_t* __restrict__ bounce, int jcol0) {
    const int tid = threadIdx.x;
    const int lane = tid & 31, w = tid >> 5;
    const int r0 = w * 32 + (lane >> 2);
    const int kq = (lane & 3) << 1;

    float acc[2][4][4];
#pragma unroll
    for (int i = 0; i < 2; ++i)
#pragma unroll
        for (int j = 0; j < 4; ++j)
#pragma unroll
            for (int k = 0; k < 4; ++k) acc[i][j][k] = 0.f;

    uint2 ab[2][8];
    ldA(ab[0], 0, src1, st1, src2, len1, r0, kq);
    ldA(ab[1], 1, src1, st1, src2, len1, r0, kq);

#pragma unroll 2
    for (int kt = 0; kt < NKT; ++kt) {
        uint2* cur = ab[kt & 1];
        uint32_t ah[2][4], al[2][4];
#pragma unroll
        for (int mt = 0; mt < 2; ++mt)
#pragma unroll
            for (int j = 0; j < 4; ++j) {
                ah[mt][j] = prmt(cur[mt * 4 + j].x, cur[mt * 4 + j].y, 0x5410);
                al[mt][j] = prmt(cur[mt * 4 + j].x, cur[mt * 4 + j].y, 0x7632);
            }
        if (kt + 2 < NKT) ldA(ab[kt & 1], kt + 2, src1, st1, src2, len1, r0, kq);

        uint2 bh[4], bl[4];
#pragma unroll
        for (int nt = 0; nt < 4; ++nt) {
            const uint32_t* wp = sW + (size_t)((nt * NKT + kt) * 2) * 64 + lane * 2;
            bh[nt] = *(const uint2*)wp;
            bl[nt] = *(const uint2*)(wp + 64);
        }
        // pass 1: hi·hi   pass 2: lo·hi   pass 3: hi·lo
#pragma unroll
        for (int mt = 0; mt < 2; ++mt)
#pragma unroll
            for (int nt = 0; nt < 4; ++nt) mma16816(acc[mt][nt], ah[mt], bh[nt]);
#pragma unroll
        for (int mt = 0; mt < 2; ++mt)
#pragma unroll
            for (int nt = 0; nt < 4; ++nt) mma16816(acc[mt][nt], al[mt], bh[nt]);
#pragma unroll
        for (int mt = 0; mt < 2; ++mt)
#pragma unroll
            for (int nt = 0; nt < 4; ++nt) mma16816(acc[mt][nt], ah[mt], bl[nt]);
    }

    // epilogue: even lanes own cells; get (g,o) from odd neighbor via shfl.xor(1)
    const int q = lane & 3;
#pragma unroll
    for (int mt = 0; mt < 2; ++mt)
#pragma unroll
        for (int nt = 0; nt < 4; ++nt) {
            float* A = acc[mt][nt];
            float e0 = __shfl_xor_sync(0xffffffffu, A[0], 1);
            float e1 = __shfl_xor_sync(0xffffffffu, A[1], 1);
            float e2 = __shfl_xor_sync(0xffffffffu, A[2], 1);
            float e3 = __shfl_xor_sync(0xffffffffu, A[3], 1);
            if (!(lane & 1)) {
                int nb = nt * 8 + 2 * q;
                float bi = sbias[nb],     bfv = sbias[nb + 1];
                float bg = sbias[nb + 2], bo  = sbias[nb + 3];
                int jc = nt * 2 + (q >> 1);
                int row = w * 32 + mt * 16 + (lane >> 2);
#pragma unroll
                for (int rp = 0; rp < 2; ++rp) {
                    float iv = A[rp * 2 + 0] + bi;
                    float fv = A[rp * 2 + 1] + bfv;
                    float gv = (rp ? e2 : e0) + bg;
                    float ov = (rp ? e3 : e1) + bo;
                    int ci = mt * 8 + rp * 4 + nt;
                    float cn = sigm(fv) * cst[ci] + sigm(iv) * tanhf(gv);
                    cst[ci] = cn;
                    bounce[(row + rp * 8) * 8 + jc] =
                        pack_split(sigm(ov) * tanhf(cn));
                }
            }
        }
    __syncthreads();
    {   // coalesced h store: 128 threads, one batch row each
        uint4 v0 = *(const uint4*)(bounce + tid * 8);
        uint4 v1 = *(const uint4*)(bounce + tid * 8 + 4);
        *(uint4*)(hOut + (size_t)tid * H_ + jcol0)     = v0;
        *(uint4*)(hOut + (size_t)tid * H_ + jcol0 + 4) = v1;
    }
}

// ---------------- persistent main kernel -----------------------------------------
__global__ void __launch_bounds__(128, 1) lstm_main() {
    extern __shared__ uint32_t smw[];          // weights + bounce
    __shared__ float s_bias[32];
    uint32_t* bounce = smw + 32768;            // after 128KB weight region

    const int cta = blockIdx.x, tid = threadIdx.x;
    const bool isL1 = (cta >= 64);
    const int lc = isL1 ? cta - 64 : cta;
    const int jcol0 = lc * 8;

    // load resident weight fragment slice (contiguous)
    {
        const uint4* src = isL1 ? g_Wf1 : g_Wf0;
        const int NKT = isL1 ? NKT1 : NKT0;
        const uint4* s = src + (size_t)lc * 4 * NKT * 2 * 16;
        uint4* d = (uint4*)smw;
        for (int i = tid; i < NKT * 128; i += 128) d[i] = s[i];
        const float* gb = isL1 ? g_b1 : g_b0;
        if (tid < 32) s_bias[tid] = gb[lc * 32 + tid];
    }
    // zero h buffers each launch (deterministic)
    for (int i = cta * 128 + tid; i < 4 * BH; i += NCTA * 128)
        ((uint32_t*)g_hp)[i] = 0u;

    unsigned relBase = *(volatile unsigned*)&g_release;
    unsigned gen = 0;
    float cst[16];
#pragma unroll
    for (int i = 0; i < 16; ++i) cst[i] = 0.f;

    gridBarrier(relBase + ++gen);

    for (int phase = 0; phase <= T_; ++phase) {
        if (!isL1) {
            if (phase < T_) {
                int t = phase;
                const uint32_t* hprev = g_hp[0][(t & 1) ^ 1];
                uint32_t* hout = g_hp[0][t & 1];
                lstm_phase<NKT0>(smw, g_xp + (size_t)t * B_ * D_, D_,
                                 hprev, D_, hout, cst, s_bias, bounce, jcol0);
            }
        } else if (phase >= 1) {
            int t = phase - 1;
            const uint32_t* h0cur = g_hp[0][t & 1];
            const uint32_t* h1prev = g_hp[1][(t & 1) ^ 1];
            uint32_t* hout = g_hp[1][t & 1];
            lstm_phase<NKT1>(smw, h0cur, H_, h1prev, H_,
                             hout, cst, s_bias, bounce, jcol0);
        }
        gridBarrier(relBase + ++gen);
    }
}

// ---------------- FC head ----------------------------------------------------------
__global__ void fc_head(const float* __restrict__ fc1w, const float* __restrict__ fc1b,
                        const float* __restrict__ fc2w, const float* __restrict__ fc2b,
                        float* __restrict__ out) {
    __shared__ float hsh[H_];
    __shared__ float hid[32];
    int b = blockIdx.x, tid = threadIdx.x;
    const uint32_t* h = g_hp[1][1] + (size_t)b * H_;   // t=511 odd -> buf1
#pragma unroll
    for (int r = 0; r < 2; ++r) {
        uint32_t u = h[tid + r * 256];
        hsh[tid + r * 256] =
            __bfloat162float(__ushort_as_bfloat16((unsigned short)(u & 0xFFFFu))) +
            __bfloat162float(__ushort_as_bfloat16((unsigned short)(u >> 16)));
    }
    __syncthreads();
    int w = tid >> 5, lane = tid & 31;
    for (int j = w; j < 32; j += 8) {
        const float* wr = fc1w + (size_t)j * H_;
        float s = 0.f;
        for (int k = lane; k < H_; k += 32) s += hsh[k] * wr[k];
#pragma unroll
        for (int off = 16; off; off >>= 1) s += __shfl_xor_sync(0xffffffffu, s, off);
        if (lane == 0) hid[j] = fmaxf(s + fc1b[j], 0.f) * fc2w[j];
    }
    __syncthreads();
    if (tid < 32) {
        float v = hid[tid];
#pragma unroll
        for (int off = 16; off; off >>= 1) v += __shfl_xor_sync(0xffffffffu, v, off);
        if (tid == 0) out[b] = v + fc2b[0];
    }
}

// ---------------- launch -------------------------------------------------------------
extern "C" void kernel_launch(void* const* d_in, const int* in_sizes, int n_in,
                              void* d_out, int out_size) {
    const float* x     = (const float*)d_in[0];
    const float* projw = (const float*)d_in[1];
    const float* projb = (const float*)d_in[2];
    const float* wx0   = (const float*)d_in[3];
    const float* bx0   = (const float*)d_in[4];
    const float* wh0   = (const float*)d_in[5];
    const float* bh0   = (const float*)d_in[6];
    const float* wx1   = (const float*)d_in[7];
    const float* bx1   = (const float*)d_in[8];
    const float* wh1   = (const float*)d_in[9];
    const float* bh1   = (const float*)d_in[10];
    const float* fc1w  = (const float*)d_in[11];
    const float* fc1b  = (const float*)d_in[12];
    const float* fc2w  = (const float*)d_in[13];
    const float* fc2b  = (const float*)d_in[14];
    float* out = (float*)d_out;

    const int SMEM_BYTES = 131072 + 4096;   // 128KB weights (L1) + 4KB bounce
    cudaFuncSetAttribute(lstm_main, cudaFuncAttributeMaxDynamicSharedMemorySize,
                         SMEM_BYTES);

    prep_x<<<2048, 256>>>(x);
    prep_w0<<<G_, D_>>>(wx0, projw, projb, bx0, bh0);
    prep_rest<<<2048, 256>>>(wh0, wx1, wh1, bx1, bh1);
    lstm_main<<<NCTA, 128, SMEM_BYTES>>>();
    fc_head<<<B_, 256>>>(fc1w, fc1b, fc2w, fc2b, out);
}

// round 9
// speedup vs baseline: 1.9578x; 1.2141x over previous
#include <cuda_runtime.h>
#include <cuda_bf16.h>
#include <cstdint>

#define B_   128
#define T_   512
#define D_   256
#define H_   512
#define G_   2048
#define K0_  768
#define K1_  1024
#define NKT0 (K0_ / 16)      // 48 ktiles
#define NKT1 (K1_ / 16)      // 64 ktiles
#define NCTA 128
#define BH   (B_ * H_)

// ---------------- persistent device scratch -----------------------------------
// Weight fragments, B-frag lane order: [ntg(256)][kt][s=hi/lo][lane(32)][4 bf16]
__device__ uint4 g_Wf0[(size_t)256 * NKT0 * 2 * 16];   // 6 MB
__device__ uint4 g_Wf1[(size_t)256 * NKT1 * 2 * 16];   // 8 MB
__device__ float g_b0[G_];
__device__ float g_b1[G_];
__device__ uint32_t g_xp[(size_t)T_ * B_ * D_];        // packed hi|lo<<16, [t][b][d]
__device__ uint32_t g_hp[2][2][BH];                    // [layer][buf][b*H + col]
__device__ unsigned g_count;
__device__ unsigned g_release;

// ---------------- helpers -------------------------------------------------------
__device__ __forceinline__ float sigm(float v) { return 1.f / (1.f + __expf(-v)); }

__device__ __forceinline__ uint32_t pack_split(float v) {
    __nv_bfloat16 h = __float2bfloat16(v);
    __nv_bfloat16 l = __float2bfloat16(v - __bfloat162float(h));
    return (uint32_t)__bfloat16_as_ushort(h) |
           ((uint32_t)__bfloat16_as_ushort(l) << 16);
}

__device__ __forceinline__ uint32_t prmt(uint32_t a, uint32_t b, uint32_t c) {
    uint32_t r;
    asm("prmt.b32 %0, %1, %2, %3;" : "=r"(r) : "r"(a), "r"(b), "r"(c));
    return r;
}

__device__ __forceinline__ void mma16816(float* d, const uint32_t* a, uint2 b) {
    asm volatile(
        "mma.sync.aligned.m16n8k16.row.col.f32.bf16.bf16.f32 "
        "{%0,%1,%2,%3}, {%4,%5,%6,%7}, {%8,%9}, {%0,%1,%2,%3};"
        : "+f"(d[0]), "+f"(d[1]), "+f"(d[2]), "+f"(d[3])
        : "r"(a[0]), "r"(a[1]), "r"(a[2]), "r"(a[3]), "r"(b.x), "r"(b.y));
}

__device__ __forceinline__ void gridBarrier(unsigned target) {
    __syncthreads();
    if (threadIdx.x == 0) {
        __threadfence();
        unsigned t = atomicAdd(&g_count, 1u);
        if (t == (unsigned)(NCTA - 1)) {
            g_count = 0;
            __threadfence();
            atomicAdd(&g_release, 1u);
        } else {
            while ((int)(*(volatile unsigned*)&g_release - target) < 0) {}
        }
        __threadfence();
    }
    __syncthreads();
}

// bf16-split store of W[np][k] into fragment layout (hi plane + lo plane)
__device__ __forceinline__ void wf_store(__nv_bfloat16* base, int NKT,
                                         int np, int k, float v) {
    __nv_bfloat16 h = __float2bfloat16(v);
    __nv_bfloat16 l = __float2bfloat16(v - __bfloat162float(h));
    int ntg = np >> 3;
    int ln = ((np & 7) << 2) | ((k >> 1) & 3);   // B-frag: n = lane/4, k-pair = lane%4
    int kt = k >> 4, b = (k >> 3) & 1, e = k & 1;
    size_t o = ((((size_t)ntg * NKT + kt) * 2) * 32 + ln) * 4 + b * 2 + e;
    base[o] = h;
    base[o + 128] = l;   // s=1 plane is +32*4 elements
}

// ---------------- prep kernels ---------------------------------------------------
__global__ void prep_x(const float* __restrict__ x) {
    const size_t total = (size_t)T_ * B_ * D_;
    for (size_t i = (size_t)blockIdx.x * blockDim.x + threadIdx.x; i < total;
         i += (size_t)gridDim.x * blockDim.x) {
        int t = (int)(i / (B_ * D_));
        int r = (int)(i % (B_ * D_));
        int b = r / D_, d = r % D_;
        g_xp[i] = pack_split(x[(size_t)b * T_ * D_ + (size_t)t * D_ + d]);
    }
}

// W0[np][k<256] = folded proj; b0
__global__ void prep_w0(const float* __restrict__ wx0, const float* __restrict__ projw,
                        const float* __restrict__ projb, const float* __restrict__ bx0,
                        const float* __restrict__ bh0) {
    int np = blockIdx.x;
    int jcol = np >> 2, q = np & 3;
    int n = q * H_ + jcol;
    int d = threadIdx.x;
    const float* wrow = wx0 + (size_t)n * D_;
    float acc = 0.f;
    for (int j = 0; j < D_; ++j) acc += wrow[j] * projw[(size_t)j * D_ + d];
    wf_store((__nv_bfloat16*)g_Wf0, NKT0, np, d, acc);
    if (d == 0) {
        float bb = bx0[n] + bh0[n];
        for (int j = 0; j < D_; ++j) bb += wrow[j] * projb[j];
        g_b0[np] = bb;
    }
}

// W0[np][k>=256] = wh0 ; W1 = [wx1|wh1] ; b1
__global__ void prep_rest(const float* __restrict__ wh0, const float* __restrict__ wx1,
                          const float* __restrict__ wh1, const float* __restrict__ bx1,
                          const float* __restrict__ bh1) {
    const int total = G_ * H_ + G_ * K1_ + G_;
    for (int i = blockIdx.x * blockDim.x + threadIdx.x; i < total;
         i += gridDim.x * blockDim.x) {
        if (i < G_ * H_) {
            int np = i / H_, k = i % H_;
            int n = (np & 3) * H_ + (np >> 2);
            wf_store((__nv_bfloat16*)g_Wf0, NKT0, np, D_ + k,
                     wh0[(size_t)n * H_ + k]);
        } else if (i < G_ * H_ + G_ * K1_) {
            int r = i - G_ * H_;
            int np = r / K1_, k = r % K1_;
            int n = (np & 3) * H_ + (np >> 2);
            float v = (k < H_) ? wx1[(size_t)n * H_ + k]
                               : wh1[(size_t)n * H_ + (k - H_)];
            wf_store((__nv_bfloat16*)g_Wf1, NKT1, np, k, v);
        } else {
            int np = i - G_ * H_ - G_ * K1_;
            int n = (np & 3) * H_ + (np >> 2);
            g_b1[np] = bx1[n] + bh1[n];
        }
    }
}

// ---------------- A fragment loads (packed u32, direct from global) -------------
// M=16 per warp: rows r0, r0+8; k pairs kq, kq+8.
__device__ __forceinline__ void ldA(uint2* a, int kt,
    const uint32_t* __restrict__ s1, int st1,
    const uint32_t* __restrict__ s2, int len1, int r0, int kq) {
    int kb = kt << 4;
    const uint32_t* s;
    int st;
    if (kb < len1) { s = s1 + kb + kq; st = st1; }
    else           { s = s2 + (kb - len1) + kq; st = H_; }
    const uint32_t* p0 = s + (size_t)r0 * st;
#pragma unroll
    for (int rp = 0; rp < 2; ++rp) {
        const uint32_t* p = p0 + (size_t)(rp * 8) * st;
        a[rp]     = *(const uint2*)p;        // a0/a1: k pair
        a[rp + 2] = *(const uint2*)(p + 8);  // a2/a3: k pair + 8
    }
}

// ---------------- one LSTM phase: bf16-split mma + cell epilogue -----------------
// 8 warps, each M=16 rows x N=32 gate-cols.
template <int NKT>
__device__ void lstm_phase(const uint32_t* __restrict__ sW,
    const uint32_t* __restrict__ src1, int st1,
    const uint32_t* __restrict__ src2, int len1,
    uint32_t* __restrict__ hOut, float* cst,
    const float* __restrict__ sbias, uint32_t* __restrict__ bounce, int jcol0) {
    const int tid = threadIdx.x;
    const int lane = tid & 31, w = tid >> 5;
    const int r0 = w * 16 + (lane >> 2);
    const int kq = (lane & 3) << 1;

    float acc[4][4];
#pragma unroll
    for (int j = 0; j < 4; ++j)
#pragma unroll
        for (int k = 0; k < 4; ++k) acc[j][k] = 0.f;

    uint2 ab[2][4];
    ldA(ab[0], 0, src1, st1, src2, len1, r0, kq);
    ldA(ab[1], 1, src1, st1, src2, len1, r0, kq);

#pragma unroll 2
    for (int kt = 0; kt < NKT; ++kt) {
        uint2* cur = ab[kt & 1];
        uint32_t ah[4], al[4];
#pragma unroll
        for (int j = 0; j < 4; ++j) {
            ah[j] = prmt(cur[j].x, cur[j].y, 0x5410);
            al[j] = prmt(cur[j].x, cur[j].y, 0x7632);
        }
        if (kt + 2 < NKT) ldA(ab[kt & 1], kt + 2, src1, st1, src2, len1, r0, kq);

        uint2 bh[4], bl[4];
#pragma unroll
        for (int nt = 0; nt < 4; ++nt) {
            const uint32_t* wp = sW + (size_t)((nt * NKT + kt) * 2) * 64 + lane * 2;
            bh[nt] = *(const uint2*)wp;
            bl[nt] = *(const uint2*)(wp + 64);
        }
        // pass 1: hi·hi   pass 2: lo·hi   pass 3: hi·lo
#pragma unroll
        for (int nt = 0; nt < 4; ++nt) mma16816(acc[nt], ah, bh[nt]);
#pragma unroll
        for (int nt = 0; nt < 4; ++nt) mma16816(acc[nt], al, bh[nt]);
#pragma unroll
        for (int nt = 0; nt < 4; ++nt) mma16816(acc[nt], ah, bl[nt]);
    }

    // epilogue: even lanes own cells; get (g,o) from odd neighbor via shfl.xor(1)
    const int q = lane & 3;
#pragma unroll
    for (int nt = 0; nt < 4; ++nt) {
        float* A = acc[nt];
        float e0 = __shfl_xor_sync(0xffffffffu, A[0], 1);
        float e1 = __shfl_xor_sync(0xffffffffu, A[1], 1);
        float e2 = __shfl_xor_sync(0xffffffffu, A[2], 1);
        float e3 = __shfl_xor_sync(0xffffffffu, A[3], 1);
        if (!(lane & 1)) {
            int nb = nt * 8 + 2 * q;
            float bi = sbias[nb],     bfv = sbias[nb + 1];
            float bg = sbias[nb + 2], bo  = sbias[nb + 3];
            int jc = nt * 2 + (q >> 1);
            int row = w * 16 + (lane >> 2);
#pragma unroll
            for (int rp = 0; rp < 2; ++rp) {
                float iv = A[rp * 2 + 0] + bi;
                float fv = A[rp * 2 + 1] + bfv;
                float gv = (rp ? e2 : e0) + bg;
                float ov = (rp ? e3 : e1) + bo;
                int ci = rp * 4 + nt;
                float cn = sigm(fv) * cst[ci] + sigm(iv) * tanhf(gv);
                cst[ci] = cn;
                bounce[(row + rp * 8) * 8 + jc] = pack_split(sigm(ov) * tanhf(cn));
            }
        }
    }
    __syncthreads();
    {   // coalesced h store: 256 threads, one uint4 each (128 rows x 8 u32)
        int m = tid >> 1, j0 = (tid & 1) << 2;
        uint4 v = *(const uint4*)(bounce + m * 8 + j0);
        *(uint4*)(hOut + (size_t)m * H_ + jcol0 + j0) = v;
    }
}

// ---------------- persistent main kernel -----------------------------------------
__global__ void __launch_bounds__(256, 1) lstm_main() {
    extern __shared__ uint32_t smw[];          // weights + bounce
    __shared__ float s_bias[32];
    uint32_t* bounce = smw + 32768;            // after 128KB weight region

    const int cta = blockIdx.x, tid = threadIdx.x;
    const bool isL1 = (cta >= 64);
    const int lc = isL1 ? cta - 64 : cta;
    const int jcol0 = lc * 8;

    // load resident weight fragment slice (contiguous)
    {
        const uint4* src = isL1 ? g_Wf1 : g_Wf0;
        const int NKT = isL1 ? NKT1 : NKT0;
        const uint4* s = src + (size_t)lc * 4 * NKT * 2 * 16;
        uint4* d = (uint4*)smw;
        for (int i = tid; i < NKT * 128; i += 256) d[i] = s[i];
        const float* gb = isL1 ? g_b1 : g_b0;
        if (tid < 32) s_bias[tid] = gb[lc * 32 + tid];
    }
    // zero h buffers each launch (deterministic)
    for (int i = cta * 256 + tid; i < 4 * BH; i += NCTA * 256)
        ((uint32_t*)g_hp)[i] = 0u;

    unsigned relBase = *(volatile unsigned*)&g_release;
    unsigned gen = 0;
    float cst[8];
#pragma unroll
    for (int i = 0; i < 8; ++i) cst[i] = 0.f;

    gridBarrier(relBase + ++gen);

    for (int phase = 0; phase <= T_; ++phase) {
        if (!isL1) {
            if (phase < T_) {
                int t = phase;
                const uint32_t* hprev = g_hp[0][(t & 1) ^ 1];
                uint32_t* hout = g_hp[0][t & 1];
                lstm_phase<NKT0>(smw, g_xp + (size_t)t * B_ * D_, D_,
                                 hprev, D_, hout, cst, s_bias, bounce, jcol0);
            }
        } else if (phase >= 1) {
            int t = phase - 1;
            const uint32_t* h0cur = g_hp[0][t & 1];
            const uint32_t* h1prev = g_hp[1][(t & 1) ^ 1];
            uint32_t* hout = g_hp[1][t & 1];
            lstm_phase<NKT1>(smw, h0cur, H_, h1prev, H_,
                             hout, cst, s_bias, bounce, jcol0);
        }
        gridBarrier(relBase + ++gen);
    }
}

// ---------------- FC head ----------------------------------------------------------
__global__ void fc_head(const float* __restrict__ fc1w, const float* __restrict__ fc1b,
                        const float* __restrict__ fc2w, const float* __restrict__ fc2b,
                        float* __restrict__ out) {
    __shared__ float hsh[H_];
    __shared__ float hid[32];
    int b = blockIdx.x, tid = threadIdx.x;
    const uint32_t* h = g_hp[1][1] + (size_t)b * H_;   // t=511 odd -> buf1
#pragma unroll
    for (int r = 0; r < 2; ++r) {
        uint32_t u = h[tid + r * 256];
        hsh[tid + r * 256] =
            __bfloat162float(__ushort_as_bfloat16((unsigned short)(u & 0xFFFFu))) +
            __bfloat162float(__ushort_as_bfloat16((unsigned short)(u >> 16)));
    }
    __syncthreads();
    int w = tid >> 5, lane = tid & 31;
    for (int j = w; j < 32; j += 8) {
        const float* wr = fc1w + (size_t)j * H_;
        float s = 0.f;
        for (int k = lane; k < H_; k += 32) s += hsh[k] * wr[k];
#pragma unroll
        for (int off = 16; off; off >>= 1) s += __shfl_xor_sync(0xffffffffu, s, off);
        if (lane == 0) hid[j] = fmaxf(s + fc1b[j], 0.f) * fc2w[j];
    }
    __syncthreads();
    if (tid < 32) {
        float v = hid[tid];
#pragma unroll
        for (int off = 16; off; off >>= 1) v += __shfl_xor_sync(0xffffffffu, v, off);
        if (tid == 0) out[b] = v + fc2b[0];
    }
}

// ---------------- launch -------------------------------------------------------------
extern "C" void kernel_launch(void* const* d_in, const int* in_sizes, int n_in,
                              void* d_out, int out_size) {
    const float* x     = (const float*)d_in[0];
    const float* projw = (const float*)d_in[1];
    const float* projb = (const float*)d_in[2];
    const float* wx0   = (const float*)d_in[3];
    const float* bx0   = (const float*)d_in[4];
    const float* wh0   = (const float*)d_in[5];
    const float* bh0   = (const float*)d_in[6];
    const float* wx1   = (const float*)d_in[7];
    const float* bx1   = (const float*)d_in[8];
    const float* wh1   = (const float*)d_in[9];
    const float* bh1   = (const float*)d_in[10];
    const float* fc1w  = (const float*)d_in[11];
    const float* fc1b  = (const float*)d_in[12];
    const float* fc2w  = (const float*)d_in[13];
    const float* fc2b  = (const float*)d_in[14];
    float* out = (float*)d_out;

    const int SMEM_BYTES = 131072 + 4096;   // 128KB weights (L1 case) + 4KB bounce
    cudaFuncSetAttribute(lstm_main, cudaFuncAttributeMaxDynamicSharedMemorySize,
                         SMEM_BYTES);

    prep_x<<<2048, 256>>>(x);
    prep_w0<<<G_, D_>>>(wx0, projw, projb, bx0, bh0);
    prep_rest<<<2048, 256>>>(wh0, wx1, wh1, bx1, bh1);
    lstm_main<<<NCTA, 256, SMEM_BYTES>>>();
    fc_head<<<B_, 256>>>(fc1w, fc1b, fc2w, fc2b, out);
}